// round 1
// baseline (speedup 1.0000x reference)
#include <cuda_runtime.h>
#include <math.h>

#define BS_    64
#define KK_    4
#define PTS_   5
#define RES_   28
#define STEPS_ 500
#define TC_    125      // t-chunk size
#define NCHUNK_ 4
#define NTHREADS_ 256
#define PIX_ (RES_*RES_)   // 784

// staging: tanh-normed strokes per (b,k)
__device__ float g_stage[BS_ * KK_ * PIX_];

__global__ __launch_bounds__(NTHREADS_)
void guide_strokes_kernel(const float* __restrict__ z_pres,
                          const float* __restrict__ z_what,
                          const float* __restrict__ z_where,
                          const float* __restrict__ sigma_p,
                          const float* __restrict__ slope_strk_p)
{
    __shared__ float Ex[TC_ * RES_];      // 3500 floats
    __shared__ float Ey[TC_ * RES_];      // 3500 floats
    __shared__ float part[4 * PIX_];      // 3136 floats
    __shared__ float red[8];

    const int bk  = blockIdx.x;           // 0..255 = b*4 + k
    const int tid = threadIdx.x;

    // ---- load transform params (uniform, L1-broadcast) ----
    const float s   = z_where[bk * 3 + 0];
    const float sh0 = z_where[bk * 3 + 1];
    const float sh1 = z_where[bk * 3 + 2];

    float px0, px1, px2, px3, px4, py0, py1, py2, py3, py4;
    {
        const float* w = z_what + bk * PTS_ * 2;
        px0 = w[0] * s + sh0;  py0 = w[1] * s + sh1;
        px1 = w[2] * s + sh0;  py1 = w[3] * s + sh1;
        px2 = w[4] * s + sh0;  py2 = w[5] * s + sh1;
        px3 = w[6] * s + sh0;  py3 = w[7] * s + sh1;
        px4 = w[8] * s + sh0;  py4 = w[9] * s + sh1;
    }
    const float sigma = *sigma_p;
    const float inv   = 1.0f / (2.0f * sigma * sigma);
    const float ninv  = -inv;

    // phase-2 thread mapping: 4 t-groups x 49 tile-threads (7x7 tiles of 4x4 px)
    const int g   = tid >> 6;     // 0..3
    const int sid = tid & 63;     // 0..63 (active if < 49)
    const int ty  = sid / 7;
    const int tx  = sid - ty * 7;

    float acc[4][4];
#pragma unroll
    for (int i = 0; i < 4; i++)
#pragma unroll
        for (int j = 0; j < 4; j++) acc[i][j] = 0.0f;

    for (int c = 0; c < NCHUNK_; c++) {
        const int t0 = c * TC_;
        __syncthreads();   // previous chunk fully consumed before overwrite

        // ---- phase 1: fill Ex/Ey rows for this chunk ----
        // one thread per (t, dim): 2*TC_ = 250 workers
        for (int w = tid; w < 2 * TC_; w += NTHREADS_) {
            const int tr  = w >> 1;
            const int isY = w & 1;
            const float u  = (float)(t0 + tr) * (1.0f / (float)(STEPS_ - 1));
            const float v  = 1.0f - u;
            const float u2 = u * u, v2 = v * v;
            const float b0 = v2 * v2;
            const float b1 = 4.0f * u * (v * v2);
            const float b2 = 6.0f * u2 * v2;
            const float b3 = 4.0f * (u2 * u) * v;
            const float b4 = u2 * u2;
            const float cx = b0*px0 + b1*px1 + b2*px2 + b3*px3 + b4*px4;
            const float cy = b0*py0 + b1*py1 + b2*py2 + b3*py3 + b4*py4;
            const float cc = isY ? cy : cx;
            float4* row4 = (float4*)(isY ? (Ey + tr * RES_) : (Ex + tr * RES_));
#pragma unroll
            for (int q = 0; q < 7; q++) {
                float4 r;
                float d0 = (float)(4*q + 0) * (1.0f/27.0f) - cc;
                float d1 = (float)(4*q + 1) * (1.0f/27.0f) - cc;
                float d2 = (float)(4*q + 2) * (1.0f/27.0f) - cc;
                float d3 = (float)(4*q + 3) * (1.0f/27.0f) - cc;
                r.x = __expf(d0 * d0 * ninv);
                r.y = __expf(d1 * d1 * ninv);
                r.z = __expf(d2 * d2 * ninv);
                r.w = __expf(d3 * d3 * ninv);
                row4[q] = r;
            }
        }
        __syncthreads();

        // ---- phase 2: rank-1 accumulation, 4x4 register tile per thread ----
        if (sid < 49) {
            const int tl0 = (TC_ * g) >> 2;
            const int tl1 = (TC_ * (g + 1)) >> 2;
#pragma unroll 4
            for (int tt = tl0; tt < tl1; tt++) {
                const float4 ex = *(const float4*)(Ex + tt * RES_ + (tx << 2));
                const float4 ey = *(const float4*)(Ey + tt * RES_ + (ty << 2));
                acc[0][0] += ey.x * ex.x; acc[0][1] += ey.x * ex.y;
                acc[0][2] += ey.x * ex.z; acc[0][3] += ey.x * ex.w;
                acc[1][0] += ey.y * ex.x; acc[1][1] += ey.y * ex.y;
                acc[1][2] += ey.y * ex.z; acc[1][3] += ey.y * ex.w;
                acc[2][0] += ey.z * ex.x; acc[2][1] += ey.z * ex.y;
                acc[2][2] += ey.z * ex.z; acc[2][3] += ey.z * ex.w;
                acc[3][0] += ey.w * ex.x; acc[3][1] += ey.w * ex.y;
                acc[3][2] += ey.w * ex.z; acc[3][3] += ey.w * ex.w;
            }
        }
    }
    __syncthreads();

    // ---- merge 4 t-group partials ----
    if (sid < 49) {
        float* pbase = part + g * PIX_;
#pragma unroll
        for (int i = 0; i < 4; i++)
#pragma unroll
            for (int j = 0; j < 4; j++)
                pbase[(ty * 4 + i) * RES_ + (tx * 4 + j)] = acc[i][j];
    }
    __syncthreads();

    // ---- epilogue: z_pres scale, maxnorm, tanh-norm, stage ----
    const float zp = z_pres[bk];
    float myv[4];
    float lmax = 0.0f;
#pragma unroll
    for (int r = 0; r < 4; r++) {
        const int p = r * NTHREADS_ + tid;
        float v = 0.0f;
        if (p < PIX_) {
            v = (part[p] + part[PIX_ + p] + part[2*PIX_ + p] + part[3*PIX_ + p]) * zp;
        }
        myv[r] = v;
        lmax = fmaxf(lmax, v);
    }
#pragma unroll
    for (int o = 16; o > 0; o >>= 1)
        lmax = fmaxf(lmax, __shfl_xor_sync(0xffffffffu, lmax, o));
    if ((tid & 31) == 0) red[tid >> 5] = lmax;
    __syncthreads();
    float bmax = red[0];
#pragma unroll
    for (int w = 1; w < 8; w++) bmax = fmaxf(bmax, red[w]);

    const float scale = 1.0f / (bmax + 1e-6f);
    const float sl    = *slope_strk_p;
    const float itsl  = 1.0f / tanhf(sl);
    float* stage = g_stage + bk * PIX_;
#pragma unroll
    for (int r = 0; r < 4; r++) {
        const int p = r * NTHREADS_ + tid;
        if (p < PIX_)
            stage[p] = tanhf(myv[r] * scale * sl) * itsl;
    }
}

__global__ __launch_bounds__(256)
void guide_compose_kernel(const float* __restrict__ slope_p,
                          float* __restrict__ out)
{
    const int i = blockIdx.x * blockDim.x + threadIdx.x;
    if (i < BS_ * PIX_) {
        const int b = i / PIX_;
        const int p = i - b * PIX_;
        const float* st = g_stage + b * KK_ * PIX_;
        const float ssum = st[p] + st[PIX_ + p] + st[2*PIX_ + p] + st[3*PIX_ + p];
        const float sl = *slope_p;
        out[i] = tanhf(ssum * sl) / tanhf(sl);
    }
}

extern "C" void kernel_launch(void* const* d_in, const int* in_sizes, int n_in,
                              void* d_out, int out_size)
{
    const float* z_pres     = (const float*)d_in[0];
    const float* z_what     = (const float*)d_in[1];
    const float* z_where    = (const float*)d_in[2];
    const float* sigma      = (const float*)d_in[3];
    const float* slope_strk = (const float*)d_in[4];
    const float* slope      = (const float*)d_in[5];
    float* out = (float*)d_out;

    guide_strokes_kernel<<<BS_ * KK_, NTHREADS_>>>(z_pres, z_what, z_where,
                                                   sigma, slope_strk);
    guide_compose_kernel<<<(BS_ * PIX_ + 255) / 256, 256>>>(slope, out);
}